// round 7
// baseline (speedup 1.0000x reference)
#include <cuda_runtime.h>
#include <cuda_bf16.h>
#include <cstdint>
#include <math.h>

#define NPTS  32768
#define CIN   64
#define NHD   16
#define CQ    1024
#define LNEPS 1e-5f

// ---------------- helpers ----------------
__device__ __forceinline__ uint32_t smem_u32(const void* p) {
    uint32_t a;
    asm("{ .reg .u64 t; cvta.to.shared.u64 t, %1; cvt.u32.u64 %0, t; }" : "=r"(a) : "l"(p));
    return a;
}
__device__ __forceinline__ void ldsm_x4(uint32_t r[4], uint32_t addr) {
    asm volatile("ldmatrix.sync.aligned.m8n8.x4.shared.b16 {%0,%1,%2,%3}, [%4];"
                 : "=r"(r[0]), "=r"(r[1]), "=r"(r[2]), "=r"(r[3]) : "r"(addr));
}
__device__ __forceinline__ void mma_bf16(float c[4], const uint32_t a[4], uint32_t b0, uint32_t b1) {
    asm volatile("mma.sync.aligned.m16n8k16.row.col.f32.bf16.bf16.f32 "
                 "{%0,%1,%2,%3}, {%4,%5,%6,%7}, {%8,%9}, {%0,%1,%2,%3};"
                 : "+f"(c[0]), "+f"(c[1]), "+f"(c[2]), "+f"(c[3])
                 : "r"(a[0]), "r"(a[1]), "r"(a[2]), "r"(a[3]), "r"(b0), "r"(b1));
}
__device__ __forceinline__ uint32_t pkb(__nv_bfloat16 a, __nv_bfloat16 b) {
    return (uint32_t)__bfloat16_as_ushort(a) | ((uint32_t)__bfloat16_as_ushort(b) << 16);
}
#define CP16(dst, src) \
    asm volatile("cp.async.ca.shared.global [%0], [%1], 16;" :: "r"((uint32_t)(dst)), "l"(src))
#define CP_COMMIT() asm volatile("cp.async.commit_group;")
#define CP_WAIT0()  asm volatile("cp.async.wait_group 0;" ::: "memory")
#define CP_WAIT1()  asm volatile("cp.async.wait_group 1;" ::: "memory")

// ---------------- scratch ----------------
__device__ float    g_xm  [NPTS * CIN];     // LN(M) fp32, [p][c]
__device__ uint32_t g_xfh [NPTS * 64];      // LN(F) bf16 split, [p][word]: 0-31 hi pairs, 32-63 lo pairs
__device__ float    g_qm  [NPTS * CQ];      // float2 planes: [(h*32+c2)][p][2]
__device__ uint32_t g_GtA [CQ * 64];        // [n][word]: [hi | lo]
__device__ uint32_t g_GtB [CQ * 64];        // [n][word]: [lo | hi]
__device__ float    g_u   [CQ];

// ---------------- kernel 0: fused weights G = Wf Wm^T (bf16 split) + u ----------------
__global__ __launch_bounds__(256) void precompute_kernel(
    const float* __restrict__ wf, const float* __restrict__ wm,
    const float* __restrict__ bf)
{
    int h = blockIdx.x;
    __shared__ float wfs[64][65];
    __shared__ float wms[64][65];
    int tid = threadIdx.x;
    for (int idx = tid; idx < 4096; idx += 256) {
        int r = idx >> 6, d = idx & 63;
        wfs[r][d] = wf[r * CQ + h * 64 + d];
        wms[r][d] = wm[r * CQ + h * 64 + d];
    }
    __syncthreads();
    for (int idx = tid; idx < 2048; idx += 256) {
        int i2 = idx >> 6, j = idx & 63;
        float s0 = 0.f, s1 = 0.f;
        #pragma unroll
        for (int d = 0; d < 64; d++) {
            s0 += wfs[2 * i2][d] * wms[j][d];
            s1 += wfs[2 * i2 + 1][d] * wms[j][d];
        }
        __nv_bfloat16 h0 = __float2bfloat16_rn(s0), h1 = __float2bfloat16_rn(s1);
        __nv_bfloat16 l0 = __float2bfloat16_rn(s0 - __bfloat162float(h0));
        __nv_bfloat16 l1 = __float2bfloat16_rn(s1 - __bfloat162float(h1));
        int n = h * 64 + j;
        uint32_t hp = pkb(h0, h1), lp = pkb(l0, l1);
        g_GtA[n * 64 + i2]      = hp;
        g_GtA[n * 64 + 32 + i2] = lp;
        g_GtB[n * 64 + i2]      = lp;
        g_GtB[n * 64 + 32 + i2] = hp;
    }
    if (tid < 64) {
        float s = 0.f;
        #pragma unroll
        for (int d = 0; d < 64; d++) s += wms[tid][d] * bf[h * 64 + d];
        g_u[h * 64 + tid] = s;
    }
}

// ---------------- kernel 1: LayerNorm ----------------
__global__ __launch_bounds__(128) void ln_kernel(
    const float* __restrict__ src,
    const float* __restrict__ gamma, const float* __restrict__ beta,
    int which)   // 0 -> bf16 split to g_xfh ; 1 -> fp32 to g_xm
{
    __shared__ float gs[64], bs[64];
    int tid = threadIdx.x;
    if (tid < 64) { gs[tid] = gamma[tid]; bs[tid] = beta[tid]; }
    __syncthreads();

    int p = blockIdx.x * 128 + tid;
    float v[64];
    float mean = 0.f;
    #pragma unroll
    for (int c = 0; c < 64; c++) { v[c] = src[c * NPTS + p]; mean += v[c]; }
    mean *= (1.f / 64.f);
    float var = 0.f;
    #pragma unroll
    for (int c = 0; c < 64; c++) { float d = v[c] - mean; var += d * d; }
    float rstd = rsqrtf(var * (1.f / 64.f) + LNEPS);

    if (which == 0) {
        #pragma unroll
        for (int c8 = 0; c8 < 64; c8 += 8) {
            uint32_t hw[4], lw[4];
            #pragma unroll
            for (int j = 0; j < 4; j++) {
                int c = c8 + 2 * j;
                float y0 = (v[c] - mean) * rstd * gs[c] + bs[c];
                float y1 = (v[c + 1] - mean) * rstd * gs[c + 1] + bs[c + 1];
                __nv_bfloat16 h0 = __float2bfloat16_rn(y0), h1 = __float2bfloat16_rn(y1);
                __nv_bfloat16 l0 = __float2bfloat16_rn(y0 - __bfloat162float(h0));
                __nv_bfloat16 l1 = __float2bfloat16_rn(y1 - __bfloat162float(h1));
                hw[j] = pkb(h0, h1);
                lw[j] = pkb(l0, l1);
            }
            *(uint4*)&g_xfh[p * 64 + (c8 >> 1)]      = make_uint4(hw[0], hw[1], hw[2], hw[3]);
            *(uint4*)&g_xfh[p * 64 + 32 + (c8 >> 1)] = make_uint4(lw[0], lw[1], lw[2], lw[3]);
        }
    } else {
        #pragma unroll
        for (int c = 0; c < 64; c += 4) {
            float4 o;
            o.x = (v[c + 0] - mean) * rstd * gs[c + 0] + bs[c + 0];
            o.y = (v[c + 1] - mean) * rstd * gs[c + 1] + bs[c + 1];
            o.z = (v[c + 2] - mean) * rstd * gs[c + 2] + bs[c + 2];
            o.w = (v[c + 3] - mean) * rstd * gs[c + 3] + bs[c + 3];
            *(float4*)&g_xm[p * 64 + c] = o;
        }
    }
}

// ---------------- kernel 2: qm GEMM via mma.sync bf16 (split, exact) ----------------
// B-resident m-loop (unchanged from R6: 70us, tensor 42%).
#define GEMM_SMEM (98304)

__global__ __launch_bounds__(256, 2) void qm_gemm_mma()
{
    extern __shared__ char smg[];
    __shared__ float su[128];
    int tid = threadIdx.x;
    int wid = tid >> 5, lane = tid & 31;
    int n0 = blockIdx.x * 128;
    int p0 = blockIdx.y * 512;
    int wm = wid & 1, wn = wid >> 1;

    if (tid < 128) su[tid] = g_u[n0 + tid];

    uint32_t smb = smem_u32(smg);
    const uint4* xf4 = (const uint4*)g_xfh;
    const uint4* GA  = (const uint4*)g_GtA;
    const uint4* GB  = (const uint4*)g_GtB;

    #pragma unroll
    for (int i = tid; i < 2048; i += 256) {
        int r = i >> 4, c = i & 15;
        uint32_t dst = r * 256 + ((c ^ (r & 7)) << 4);
        CP16(smb + 32768 + dst, &GA[(n0 + r) * 16 + c]);
        CP16(smb + 65536 + dst, &GB[(n0 + r) * 16 + c]);
    }
    #pragma unroll
    for (int i = tid; i < 1024; i += 256) {
        int r = i >> 4, c = i & 15;
        uint32_t dst = r * 256 + ((c ^ (r & 7)) << 4);
        CP16(smb + dst, &xf4[(p0 + r) * 16 + c]);
    }
    CP_COMMIT();

    int arow = wm * 32 + (lane & 15);
    int ach  = lane >> 4;
    int brow = wn * 32 + (lane & 7) + ((lane >> 4) << 3);
    int bch  = (lane >> 3) & 1;
    int g = lane >> 2, t4 = lane & 3;
    float2* q2 = (float2*)g_qm;

    #pragma unroll 1
    for (int t = 0; t < 8; t++) {
        __syncthreads();
        if (t < 7) {
            uint32_t abase = ((t + 1) & 1) ? 16384u : 0u;
            int pr = p0 + (t + 1) * 64;
            #pragma unroll
            for (int i = tid; i < 1024; i += 256) {
                int r = i >> 4, c = i & 15;
                uint32_t dst = abase + r * 256 + ((c ^ (r & 7)) << 4);
                CP16(smb + dst, &xf4[(pr + r) * 16 + c]);
            }
            CP_COMMIT();
            CP_WAIT1();
        } else {
            CP_WAIT0();
        }
        __syncthreads();

        uint32_t abase = (t & 1) ? 16384u : 0u;
        float acc[2][4][4];
        #pragma unroll
        for (int mi = 0; mi < 2; mi++)
            #pragma unroll
            for (int ni = 0; ni < 4; ni++)
                #pragma unroll
                for (int e = 0; e < 4; e++) acc[mi][ni][e] = 0.f;

        #pragma unroll
        for (int ks = 0; ks < 16; ks++) {
            int kk = ks & 7;
            uint32_t boff = (ks < 8) ? 32768u : 65536u;
            uint32_t a[2][4];
            #pragma unroll
            for (int mi = 0; mi < 2; mi++) {
                int row = arow + mi * 16;
                int ch  = kk * 2 + ach;
                ldsm_x4(a[mi], smb + abase + row * 256 + ((ch ^ (row & 7)) << 4));
            }
            uint32_t b[2][4];
            #pragma unroll
            for (int nj = 0; nj < 2; nj++) {
                int row = brow + nj * 16;
                int ch  = kk * 2 + bch;
                ldsm_x4(b[nj], smb + boff + row * 256 + ((ch ^ (row & 7)) << 4));
            }
            #pragma unroll
            for (int mi = 0; mi < 2; mi++)
                #pragma unroll
                for (int nj = 0; nj < 2; nj++) {
                    mma_bf16(acc[mi][2 * nj + 0], a[mi], b[nj][0], b[nj][1]);
                    mma_bf16(acc[mi][2 * nj + 1], a[mi], b[nj][2], b[nj][3]);
                }
        }

        #pragma unroll
        for (int mi = 0; mi < 2; mi++) {
            int pA = p0 + t * 64 + wm * 32 + mi * 16 + g;
            #pragma unroll
            for (int ni = 0; ni < 4; ni++) {
                int nl = wn * 32 + ni * 8 + 2 * t4;
                int ng = n0 + nl;
                int h = ng >> 6, c2 = (ng & 63) >> 1;
                long base = (long)(h * 32 + c2) * NPTS;
                float u0 = su[nl], u1 = su[nl + 1];
                q2[base + pA]     = make_float2(acc[mi][ni][0] + u0, acc[mi][ni][1] + u1);
                q2[base + pA + 8] = make_float2(acc[mi][ni][2] + u0, acc[mi][ni][3] + u1);
            }
        }
    }
}

// ---------------- kernel 3: neighborhood attention, t-paired ----------------
// Tile 1z x 2y x 32t (64 pts). 256 threads = 8 head-slots (1 warp each, 2 heads)
// x 32 point-slots (lane = ts*2+py, 2 t-points each). Halo [c4][hz3][hy4][ht35]
// float4 — stride 35 + lane interleave makes the stride-32B window conflict-free.
// Per thread per c4: 36 LDS.128 feed 432 FFMA (24:1).
__global__ __launch_bounds__(256) void attn_kernel(
    const float* __restrict__ rpb, float* __restrict__ out)
{
    extern __shared__ float4 halo[];    // [c4=16][hz=3][hy=4][ht=35]
    __shared__ float rpb_s[NHD * 27];

    int tid = threadIdx.x;
    int z  = blockIdx.x >> 4;           // 0..31
    int y0 = (blockIdx.x & 15) * 2;     // 0..30

    for (int i = tid; i < NHD * 27; i += 256) rpb_s[i] = rpb[i];

    const float4* xm4 = (const float4*)g_xm;
    for (int i = tid; i < 6528; i += 256) {       // 16 c4 * 408 positions
        int c4 = i / 408;
        int r  = i - c4 * 408;
        int hz = r / 136;
        int r2 = r - hz * 136;
        int hy = r2 / 34;
        int ht = r2 - hy * 34;
        int gz = z - 1 + hz, gy = y0 - 1 + hy, gt = ht - 1;
        float4 v = make_float4(0.f, 0.f, 0.f, 0.f);
        if ((unsigned)gz < 32u && (unsigned)gy < 32u && (unsigned)gt < 32u)
            v = xm4[(gz * 1024 + gy * 32 + gt) * 16 + c4];
        halo[((c4 * 3 + hz) * 4 + hy) * 35 + ht] = v;
    }
    __syncthreads();

    int lane = tid & 31;
    int h0 = (tid >> 5) * 2;            // head pair {h0, h0+1}
    int ts = lane >> 1;                 // 0..15
    int py = lane & 1;                  // interleaved rows (bank-conflict fix)
    int t0 = ts * 2;
    int gp = z * 1024 + (y0 + py) * 32 + t0;   // point 0; point 1 = gp+1
    const float2* qm2 = (const float2*)g_qm;

    // scores [h][p][27]
    float sc[2][2][27];
    #pragma unroll
    for (int h = 0; h < 2; h++)
        #pragma unroll
        for (int o = 0; o < 27; o++) {
            float r = rpb_s[(h0 + h) * 27 + o];
            sc[h][0][o] = r;
            sc[h][1][o] = r;
        }

    // q regs: qa[h] = plane 2*c4 (ch 0,1 of this c4 for p0|p1), qb[h] = plane 2*c4+1
    float4 qa[2], qb[2], qan[2], qbn[2];
    #pragma unroll
    for (int h = 0; h < 2; h++) {
        qa[h] = *(const float4*)&qm2[((h0 + h) * 32 + 0) * NPTS + gp];
        qb[h] = *(const float4*)&qm2[((h0 + h) * 32 + 1) * NPTS + gp];
    }

    #pragma unroll 1
    for (int c4 = 0; c4 < 16; c4++) {
        if (c4 < 15) {
            #pragma unroll
            for (int h = 0; h < 2; h++) {
                qan[h] = *(const float4*)&qm2[((h0 + h) * 32 + 2 * c4 + 2) * NPTS + gp];
                qbn[h] = *(const float4*)&qm2[((h0 + h) * 32 + 2 * c4 + 3) * NPTS + gp];
            }
        }
        #pragma unroll
        for (int dz = 0; dz < 3; dz++)
            #pragma unroll
            for (int dy = 0; dy < 3; dy++) {
                const float4* rowp = &halo[((c4 * 3 + dz) * 4 + (py + dy)) * 35 + t0];
                float4 kv0 = rowp[0], kv1 = rowp[1], kv2 = rowp[2], kv3 = rowp[3];
                #pragma unroll
                for (int dx = 0; dx < 3; dx++) {
                    int o = (dz * 3 + dy) * 3 + dx;
                    float4 k0 = (dx == 0) ? kv0 : (dx == 1) ? kv1 : kv2;  // point 0
                    float4 k1 = (dx == 0) ? kv1 : (dx == 1) ? kv2 : kv3;  // point 1
                    #pragma unroll
                    for (int h = 0; h < 2; h++) {
                        float s0 = sc[h][0][o];
                        s0 = fmaf(qa[h].x, k0.x, s0);
                        s0 = fmaf(qa[h].y, k0.y, s0);
                        s0 = fmaf(qb[h].x, k0.z, s0);
                        s0 = fmaf(qb[h].y, k0.w, s0);
                        sc[h][0][o] = s0;
                        float s1 = sc[h][1][o];
                        s1 = fmaf(qa[h].z, k1.x, s1);
                        s1 = fmaf(qa[h].w, k1.y, s1);
                        s1 = fmaf(qb[h].z, k1.z, s1);
                        s1 = fmaf(qb[h].w, k1.w, s1);
                        sc[h][1][o] = s1;
                    }
                }
            }
        #pragma unroll
        for (int h = 0; h < 2; h++) { qa[h] = qan[h]; qb[h] = qbn[h]; }
    }

    // softmax + value-grid projection per (h, p)
    #pragma unroll
    for (int h = 0; h < 2; h++)
        #pragma unroll
        for (int p = 0; p < 2; p++) {
            const float* s = sc[h][p];
            float m = s[0];
            #pragma unroll
            for (int o = 1; o < 27; o++) m = fmaxf(m, s[o]);
            float sum = 0.f, xz = 0.f, xy = 0.f, xt = 0.f;
            #pragma unroll
            for (int dz = 0; dz < 3; dz++)
                #pragma unroll
                for (int dy = 0; dy < 3; dy++)
                    #pragma unroll
                    for (int dx = 0; dx < 3; dx++) {
                        int o = (dz * 3 + dy) * 3 + dx;
                        float e = __expf(s[o] - m);
                        sum += e;
                        xz += e * (float)(dz - 1);
                        xy += e * (float)(dy - 1);
                        xt += e * (float)(dx - 1);
                    }
            float inv = 1.f / sum;
            int hh = h0 + h;
            out[(hh * 3 + 0) * NPTS + gp + p] = xz * inv;
            out[(hh * 3 + 1) * NPTS + gp + p] = xy * inv;
            out[(hh * 3 + 2) * NPTS + gp + p] = xt * inv;
        }
}

// ---------------- launch ----------------
extern "C" void kernel_launch(void* const* d_in, const int* in_sizes, int n_in,
                              void* d_out, int out_size)
{
    const float* F       = (const float*)d_in[0];
    const float* M       = (const float*)d_in[1];
    const float* gamma_f = (const float*)d_in[2];
    const float* beta_f  = (const float*)d_in[3];
    const float* w_f     = (const float*)d_in[4];
    const float* b_f     = (const float*)d_in[5];
    const float* gamma_m = (const float*)d_in[6];
    const float* beta_m  = (const float*)d_in[7];
    const float* w_m     = (const float*)d_in[8];
    /* b_m (d_in[9]) is softmax-invariant and drops out */
    const float* rpb     = (const float*)d_in[10];
    float* out = (float*)d_out;

    precompute_kernel<<<16, 256>>>(w_f, w_m, b_f);
    ln_kernel<<<NPTS / 128, 128>>>(F, gamma_f, beta_f, 0);
    ln_kernel<<<NPTS / 128, 128>>>(M, gamma_m, beta_m, 1);

    cudaFuncSetAttribute(qm_gemm_mma, cudaFuncAttributeMaxDynamicSharedMemorySize, GEMM_SMEM);
    qm_gemm_mma<<<dim3(8, 64), 256, GEMM_SMEM>>>();

    const int haloBytes = 16 * 3 * 4 * 35 * (int)sizeof(float4);   // 107520
    cudaFuncSetAttribute(attn_kernel, cudaFuncAttributeMaxDynamicSharedMemorySize, haloBytes);
    attn_kernel<<<512, 256, haloBytes>>>(rpb, out);
}

// round 8
// speedup vs baseline: 1.0872x; 1.0872x over previous
#include <cuda_runtime.h>
#include <cuda_bf16.h>
#include <cstdint>
#include <math.h>

#define NPTS  32768
#define CIN   64
#define NHD   16
#define CQ    1024
#define LNEPS 1e-5f

// ---------------- helpers ----------------
__device__ __forceinline__ uint32_t smem_u32(const void* p) {
    uint32_t a;
    asm("{ .reg .u64 t; cvta.to.shared.u64 t, %1; cvt.u32.u64 %0, t; }" : "=r"(a) : "l"(p));
    return a;
}
__device__ __forceinline__ void ldsm_x4(uint32_t r[4], uint32_t addr) {
    asm volatile("ldmatrix.sync.aligned.m8n8.x4.shared.b16 {%0,%1,%2,%3}, [%4];"
                 : "=r"(r[0]), "=r"(r[1]), "=r"(r[2]), "=r"(r[3]) : "r"(addr));
}
__device__ __forceinline__ void mma_bf16(float c[4], const uint32_t a[4], uint32_t b0, uint32_t b1) {
    asm volatile("mma.sync.aligned.m16n8k16.row.col.f32.bf16.bf16.f32 "
                 "{%0,%1,%2,%3}, {%4,%5,%6,%7}, {%8,%9}, {%0,%1,%2,%3};"
                 : "+f"(c[0]), "+f"(c[1]), "+f"(c[2]), "+f"(c[3])
                 : "r"(a[0]), "r"(a[1]), "r"(a[2]), "r"(a[3]), "r"(b0), "r"(b1));
}
__device__ __forceinline__ uint32_t pkb(__nv_bfloat16 a, __nv_bfloat16 b) {
    return (uint32_t)__bfloat16_as_ushort(a) | ((uint32_t)__bfloat16_as_ushort(b) << 16);
}
#define CP16(dst, src) \
    asm volatile("cp.async.ca.shared.global [%0], [%1], 16;" :: "r"((uint32_t)(dst)), "l"(src))
#define CP_COMMIT() asm volatile("cp.async.commit_group;")
#define CP_WAIT0()  asm volatile("cp.async.wait_group 0;" ::: "memory")
#define CP_WAIT1()  asm volatile("cp.async.wait_group 1;" ::: "memory")

// ---------------- scratch ----------------
__device__ float    g_xm  [NPTS * CIN];     // LN(M) fp32, [p][c]
__device__ uint32_t g_xfh [NPTS * 64];      // LN(F) bf16 split, [p][word]: 0-31 hi pairs, 32-63 lo pairs
__device__ float    g_qm  [NPTS * CQ];      // float2 planes: [(h*32+c2)][p][2]
__device__ uint32_t g_GtA [CQ * 64];        // [n][word]: [hi | lo]
__device__ uint32_t g_GtB [CQ * 64];        // [n][word]: [lo | hi]
__device__ float    g_u   [CQ];

// ---------------- kernel 0: fused weights G = Wf Wm^T (bf16 split) + u ----------------
__global__ __launch_bounds__(256) void precompute_kernel(
    const float* __restrict__ wf, const float* __restrict__ wm,
    const float* __restrict__ bf)
{
    int h = blockIdx.x;
    __shared__ float wfs[64][65];
    __shared__ float wms[64][65];
    int tid = threadIdx.x;
    for (int idx = tid; idx < 4096; idx += 256) {
        int r = idx >> 6, d = idx & 63;
        wfs[r][d] = wf[r * CQ + h * 64 + d];
        wms[r][d] = wm[r * CQ + h * 64 + d];
    }
    __syncthreads();
    for (int idx = tid; idx < 2048; idx += 256) {
        int i2 = idx >> 6, j = idx & 63;
        float s0 = 0.f, s1 = 0.f;
        #pragma unroll
        for (int d = 0; d < 64; d++) {
            s0 += wfs[2 * i2][d] * wms[j][d];
            s1 += wfs[2 * i2 + 1][d] * wms[j][d];
        }
        __nv_bfloat16 h0 = __float2bfloat16_rn(s0), h1 = __float2bfloat16_rn(s1);
        __nv_bfloat16 l0 = __float2bfloat16_rn(s0 - __bfloat162float(h0));
        __nv_bfloat16 l1 = __float2bfloat16_rn(s1 - __bfloat162float(h1));
        int n = h * 64 + j;
        uint32_t hp = pkb(h0, h1), lp = pkb(l0, l1);
        g_GtA[n * 64 + i2]      = hp;
        g_GtA[n * 64 + 32 + i2] = lp;
        g_GtB[n * 64 + i2]      = lp;
        g_GtB[n * 64 + 32 + i2] = hp;
    }
    if (tid < 64) {
        float s = 0.f;
        #pragma unroll
        for (int d = 0; d < 64; d++) s += wms[tid][d] * bf[h * 64 + d];
        g_u[h * 64 + tid] = s;
    }
}

// ---------------- kernel 1: LayerNorm ----------------
__global__ __launch_bounds__(128) void ln_kernel(
    const float* __restrict__ src,
    const float* __restrict__ gamma, const float* __restrict__ beta,
    int which)   // 0 -> bf16 split to g_xfh ; 1 -> fp32 to g_xm
{
    __shared__ float gs[64], bs[64];
    int tid = threadIdx.x;
    if (tid < 64) { gs[tid] = gamma[tid]; bs[tid] = beta[tid]; }
    __syncthreads();

    int p = blockIdx.x * 128 + tid;
    float v[64];
    float mean = 0.f;
    #pragma unroll
    for (int c = 0; c < 64; c++) { v[c] = src[c * NPTS + p]; mean += v[c]; }
    mean *= (1.f / 64.f);
    float var = 0.f;
    #pragma unroll
    for (int c = 0; c < 64; c++) { float d = v[c] - mean; var += d * d; }
    float rstd = rsqrtf(var * (1.f / 64.f) + LNEPS);

    if (which == 0) {
        #pragma unroll
        for (int c8 = 0; c8 < 64; c8 += 8) {
            uint32_t hw[4], lw[4];
            #pragma unroll
            for (int j = 0; j < 4; j++) {
                int c = c8 + 2 * j;
                float y0 = (v[c] - mean) * rstd * gs[c] + bs[c];
                float y1 = (v[c + 1] - mean) * rstd * gs[c + 1] + bs[c + 1];
                __nv_bfloat16 h0 = __float2bfloat16_rn(y0), h1 = __float2bfloat16_rn(y1);
                __nv_bfloat16 l0 = __float2bfloat16_rn(y0 - __bfloat162float(h0));
                __nv_bfloat16 l1 = __float2bfloat16_rn(y1 - __bfloat162float(h1));
                hw[j] = pkb(h0, h1);
                lw[j] = pkb(l0, l1);
            }
            *(uint4*)&g_xfh[p * 64 + (c8 >> 1)]      = make_uint4(hw[0], hw[1], hw[2], hw[3]);
            *(uint4*)&g_xfh[p * 64 + 32 + (c8 >> 1)] = make_uint4(lw[0], lw[1], lw[2], lw[3]);
        }
    } else {
        #pragma unroll
        for (int c = 0; c < 64; c += 4) {
            float4 o;
            o.x = (v[c + 0] - mean) * rstd * gs[c + 0] + bs[c + 0];
            o.y = (v[c + 1] - mean) * rstd * gs[c + 1] + bs[c + 1];
            o.z = (v[c + 2] - mean) * rstd * gs[c + 2] + bs[c + 2];
            o.w = (v[c + 3] - mean) * rstd * gs[c + 3] + bs[c + 3];
            *(float4*)&g_xm[p * 64 + c] = o;
        }
    }
}

// ---------------- kernel 2: qm GEMM via mma.sync bf16 (split, exact) ----------------
// B-resident m-loop (unchanged from R6: ~69us).
#define GEMM_SMEM (98304)

__global__ __launch_bounds__(256, 2) void qm_gemm_mma()
{
    extern __shared__ char smg[];
    __shared__ float su[128];
    int tid = threadIdx.x;
    int wid = tid >> 5, lane = tid & 31;
    int n0 = blockIdx.x * 128;
    int p0 = blockIdx.y * 512;
    int wm = wid & 1, wn = wid >> 1;

    if (tid < 128) su[tid] = g_u[n0 + tid];

    uint32_t smb = smem_u32(smg);
    const uint4* xf4 = (const uint4*)g_xfh;
    const uint4* GA  = (const uint4*)g_GtA;
    const uint4* GB  = (const uint4*)g_GtB;

    #pragma unroll
    for (int i = tid; i < 2048; i += 256) {
        int r = i >> 4, c = i & 15;
        uint32_t dst = r * 256 + ((c ^ (r & 7)) << 4);
        CP16(smb + 32768 + dst, &GA[(n0 + r) * 16 + c]);
        CP16(smb + 65536 + dst, &GB[(n0 + r) * 16 + c]);
    }
    #pragma unroll
    for (int i = tid; i < 1024; i += 256) {
        int r = i >> 4, c = i & 15;
        uint32_t dst = r * 256 + ((c ^ (r & 7)) << 4);
        CP16(smb + dst, &xf4[(p0 + r) * 16 + c]);
    }
    CP_COMMIT();

    int arow = wm * 32 + (lane & 15);
    int ach  = lane >> 4;
    int brow = wn * 32 + (lane & 7) + ((lane >> 4) << 3);
    int bch  = (lane >> 3) & 1;
    int g = lane >> 2, t4 = lane & 3;
    float2* q2 = (float2*)g_qm;

    #pragma unroll 1
    for (int t = 0; t < 8; t++) {
        __syncthreads();
        if (t < 7) {
            uint32_t abase = ((t + 1) & 1) ? 16384u : 0u;
            int pr = p0 + (t + 1) * 64;
            #pragma unroll
            for (int i = tid; i < 1024; i += 256) {
                int r = i >> 4, c = i & 15;
                uint32_t dst = abase + r * 256 + ((c ^ (r & 7)) << 4);
                CP16(smb + dst, &xf4[(pr + r) * 16 + c]);
            }
            CP_COMMIT();
            CP_WAIT1();
        } else {
            CP_WAIT0();
        }
        __syncthreads();

        uint32_t abase = (t & 1) ? 16384u : 0u;
        float acc[2][4][4];
        #pragma unroll
        for (int mi = 0; mi < 2; mi++)
            #pragma unroll
            for (int ni = 0; ni < 4; ni++)
                #pragma unroll
                for (int e = 0; e < 4; e++) acc[mi][ni][e] = 0.f;

        #pragma unroll
        for (int ks = 0; ks < 16; ks++) {
            int kk = ks & 7;
            uint32_t boff = (ks < 8) ? 32768u : 65536u;
            uint32_t a[2][4];
            #pragma unroll
            for (int mi = 0; mi < 2; mi++) {
                int row = arow + mi * 16;
                int ch  = kk * 2 + ach;
                ldsm_x4(a[mi], smb + abase + row * 256 + ((ch ^ (row & 7)) << 4));
            }
            uint32_t b[2][4];
            #pragma unroll
            for (int nj = 0; nj < 2; nj++) {
                int row = brow + nj * 16;
                int ch  = kk * 2 + bch;
                ldsm_x4(b[nj], smb + boff + row * 256 + ((ch ^ (row & 7)) << 4));
            }
            #pragma unroll
            for (int mi = 0; mi < 2; mi++)
                #pragma unroll
                for (int nj = 0; nj < 2; nj++) {
                    mma_bf16(acc[mi][2 * nj + 0], a[mi], b[nj][0], b[nj][1]);
                    mma_bf16(acc[mi][2 * nj + 1], a[mi], b[nj][2], b[nj][3]);
                }
        }

        #pragma unroll
        for (int mi = 0; mi < 2; mi++) {
            int pA = p0 + t * 64 + wm * 32 + mi * 16 + g;
            #pragma unroll
            for (int ni = 0; ni < 4; ni++) {
                int nl = wn * 32 + ni * 8 + 2 * t4;
                int ng = n0 + nl;
                int h = ng >> 6, c2 = (ng & 63) >> 1;
                long base = (long)(h * 32 + c2) * NPTS;
                float u0 = su[nl], u1 = su[nl + 1];
                q2[base + pA]     = make_float2(acc[mi][ni][0] + u0, acc[mi][ni][1] + u1);
                q2[base + pA + 8] = make_float2(acc[mi][ni][2] + u0, acc[mi][ni][3] + u1);
            }
        }
    }
}

// ---------------- kernel 3: neighborhood attention (R6 layout + row pipelining) ----------------
// 512 thr, tile 2z x 2y x 32t, halo [c4=16][hz4][hy4][ht34] float4 (139 KB).
// Inner loop software-pipelined at (dz,dy)-row granularity: load row r+1
// (3x LDS.128) interleaved with FMA of row r (24 FFMA) to break warp phase-lock
// between the LDS-burst and FFMA-burst phases.
__global__ __launch_bounds__(512) void attn_kernel(
    const float* __restrict__ rpb, float* __restrict__ out)
{
    extern __shared__ float4 halo[];    // [c4=16][hz=4][hy=4][ht=34]
    __shared__ float rpb_s[NHD * 27];

    int tid = threadIdx.x;
    int z0 = (blockIdx.x >> 4) * 2;
    int y0 = (blockIdx.x & 15) * 2;

    for (int i = tid; i < NHD * 27; i += 512) rpb_s[i] = rpb[i];

    const float4* xm4 = (const float4*)g_xm;
    for (int i = tid; i < 8704; i += 512) {
        int c4 = i / 544;
        int r  = i - c4 * 544;
        int hz = r / 136;
        int r2 = r - hz * 136;
        int hy = r2 / 34;
        int ht = r2 - hy * 34;
        int gz = z0 - 1 + hz, gy = y0 - 1 + hy, gt = ht - 1;
        float4 v = make_float4(0.f, 0.f, 0.f, 0.f);
        if ((unsigned)gz < 32u && (unsigned)gy < 32u && (unsigned)gt < 32u)
            v = xm4[(gz * 1024 + gy * 32 + gt) * 16 + c4];
        halo[((c4 * 4 + hz) * 4 + hy) * 34 + ht] = v;
    }
    __syncthreads();

    int quarter = tid >> 7;
    int ptid = tid & 127;
    int pz = ptid >> 6, py = (ptid >> 5) & 1, pt = ptid & 31;
    int gp = (z0 + pz) * 1024 + (y0 + py) * 32 + pt;
    const float2* qm2 = (const float2*)g_qm;

    #pragma unroll 1
    for (int hg = 0; hg < 2; hg++) {
        int h0 = 2 * (quarter + 4 * hg);    // head pair {h0, h0+1}

        float sc0[27], sc1[27];
        #pragma unroll
        for (int o = 0; o < 27; o++) {
            sc0[o] = rpb_s[h0 * 27 + o];
            sc1[o] = rpb_s[(h0 + 1) * 27 + o];
        }

        float2 a0 = qm2[(h0 * 32 + 0) * NPTS + gp];
        float2 a1 = qm2[(h0 * 32 + 1) * NPTS + gp];
        float2 b0 = qm2[((h0 + 1) * 32 + 0) * NPTS + gp];
        float2 b1 = qm2[((h0 + 1) * 32 + 1) * NPTS + gp];
        float4 q0 = make_float4(a0.x, a0.y, a1.x, a1.y);
        float4 q1 = make_float4(b0.x, b0.y, b1.x, b1.y);
        float4 q0n, q1n;

        #pragma unroll 1
        for (int c4 = 0; c4 < 16; c4++) {
            if (c4 < 15) {
                float2 c0 = qm2[(h0 * 32 + 2 * c4 + 2) * NPTS + gp];
                float2 c1 = qm2[(h0 * 32 + 2 * c4 + 3) * NPTS + gp];
                float2 d0 = qm2[((h0 + 1) * 32 + 2 * c4 + 2) * NPTS + gp];
                float2 d1 = qm2[((h0 + 1) * 32 + 2 * c4 + 3) * NPTS + gp];
                q0n = make_float4(c0.x, c0.y, c1.x, c1.y);
                q1n = make_float4(d0.x, d0.y, d1.x, d1.y);
            }

            // ---- row-pipelined QK: 9 rows of (3 loads + 24 FFMA) ----
            const float4* rp0 = &halo[((c4 * 4 + pz) * 4 + py) * 34 + pt];
            float4 n0v = rp0[0], n1v = rp0[1], n2v = rp0[2];
            #pragma unroll
            for (int r = 0; r < 9; r++) {
                float4 k0 = n0v, k1 = n1v, k2 = n2v;
                if (r < 8) {
                    int rn = r + 1;
                    int dzn = rn / 3, dyn = rn - dzn * 3;
                    const float4* np = &halo[((c4 * 4 + pz + dzn) * 4 + (py + dyn)) * 34 + pt];
                    n0v = np[0]; n1v = np[1]; n2v = np[2];
                }
                int ob = r * 3;
                // dx = 0
                sc0[ob + 0] = fmaf(q0.x, k0.x, sc0[ob + 0]);
                sc1[ob + 0] = fmaf(q1.x, k0.x, sc1[ob + 0]);
                sc0[ob + 0] = fmaf(q0.y, k0.y, sc0[ob + 0]);
                sc1[ob + 0] = fmaf(q1.y, k0.y, sc1[ob + 0]);
                sc0[ob + 0] = fmaf(q0.z, k0.z, sc0[ob + 0]);
                sc1[ob + 0] = fmaf(q1.z, k0.z, sc1[ob + 0]);
                sc0[ob + 0] = fmaf(q0.w, k0.w, sc0[ob + 0]);
                sc1[ob + 0] = fmaf(q1.w, k0.w, sc1[ob + 0]);
                // dx = 1
                sc0[ob + 1] = fmaf(q0.x, k1.x, sc0[ob + 1]);
                sc1[ob + 1] = fmaf(q1.x, k1.x, sc1[ob + 1]);
                sc0[ob + 1] = fmaf(q0.y, k1.y, sc0[ob + 1]);
                sc1[ob + 1] = fmaf(q1.y, k1.y, sc1[ob + 1]);
                sc0[ob + 1] = fmaf(q0.z, k1.z, sc0[ob + 1]);
                sc1[ob + 1] = fmaf(q1.z, k1.z, sc1[ob + 1]);
                sc0[ob + 1] = fmaf(q0.w, k1.w, sc0[ob + 1]);
                sc1[ob + 1] = fmaf(q1.w, k1.w, sc1[ob + 1]);
                // dx = 2
                sc0[ob + 2] = fmaf(q0.x, k2.x, sc0[ob + 2]);
                sc1[ob + 2] = fmaf(q1.x, k2.x, sc1[ob + 2]);
                sc0[ob + 2] = fmaf(q0.y, k2.y, sc0[ob + 2]);
                sc1[ob + 2] = fmaf(q1.y, k2.y, sc1[ob + 2]);
                sc0[ob + 2] = fmaf(q0.z, k2.z, sc0[ob + 2]);
                sc1[ob + 2] = fmaf(q1.z, k2.z, sc1[ob + 2]);
                sc0[ob + 2] = fmaf(q0.w, k2.w, sc0[ob + 2]);
                sc1[ob + 2] = fmaf(q1.w, k2.w, sc1[ob + 2]);
            }
            q0 = q0n; q1 = q1n;
        }

        #pragma unroll
        for (int w = 0; w < 2; w++) {
            const float* s = w ? sc1 : sc0;
            int h = h0 + w;
            float m = s[0];
            #pragma unroll
            for (int o = 1; o < 27; o++) m = fmaxf(m, s[o]);
            float sum = 0.f, xz = 0.f, xy = 0.f, xt = 0.f;
            #pragma unroll
            for (int dz = 0; dz < 3; dz++)
                #pragma unroll
                for (int dy = 0; dy < 3; dy++)
                    #pragma unroll
                    for (int dx = 0; dx < 3; dx++) {
                        int o = (dz * 3 + dy) * 3 + dx;
                        float e = __expf(s[o] - m);
                        sum += e;
                        xz += e * (float)(dz - 1);
                        xy += e * (float)(dy - 1);
                        xt += e * (float)(dx - 1);
                    }
            float inv = 1.f / sum;
            out[(h * 3 + 0) * NPTS + gp] = xz * inv;
            out[(h * 3 + 1) * NPTS + gp] = xy * inv;
            out[(h * 3 + 2) * NPTS + gp] = xt * inv;
        }
    }
}

// ---------------- launch ----------------
extern "C" void kernel_launch(void* const* d_in, const int* in_sizes, int n_in,
                              void* d_out, int out_size)
{
    const float* F       = (const float*)d_in[0];
    const float* M       = (const float*)d_in[1];
    const float* gamma_f = (const float*)d_in[2];
    const float* beta_f  = (const float*)d_in[3];
    const float* w_f     = (const float*)d_in[4];
    const float* b_f     = (const float*)d_in[5];
    const float* gamma_m = (const float*)d_in[6];
    const float* beta_m  = (const float*)d_in[7];
    const float* w_m     = (const float*)d_in[8];
    /* b_m (d_in[9]) is softmax-invariant and drops out */
    const float* rpb     = (const float*)d_in[10];
    float* out = (float*)d_out;

    precompute_kernel<<<16, 256>>>(w_f, w_m, b_f);
    ln_kernel<<<NPTS / 128, 128>>>(F, gamma_f, beta_f, 0);
    ln_kernel<<<NPTS / 128, 128>>>(M, gamma_m, beta_m, 1);

    cudaFuncSetAttribute(qm_gemm_mma, cudaFuncAttributeMaxDynamicSharedMemorySize, GEMM_SMEM);
    qm_gemm_mma<<<dim3(8, 64), 256, GEMM_SMEM>>>();

    const int haloBytes = 16 * 4 * 4 * 34 * (int)sizeof(float4);   // 139264
    cudaFuncSetAttribute(attn_kernel, cudaFuncAttributeMaxDynamicSharedMemorySize, haloBytes);
    attn_kernel<<<256, 512, haloBytes>>>(rpb, out);
}

// round 9
// speedup vs baseline: 1.0888x; 1.0014x over previous
#include <cuda_runtime.h>
#include <cuda_bf16.h>
#include <cstdint>
#include <math.h>

#define NPTS  32768
#define CIN   64
#define NHD   16
#define CQ    1024
#define LNEPS 1e-5f

// ---------------- helpers ----------------
__device__ __forceinline__ uint32_t smem_u32(const void* p) {
    uint32_t a;
    asm("{ .reg .u64 t; cvta.to.shared.u64 t, %1; cvt.u32.u64 %0, t; }" : "=r"(a) : "l"(p));
    return a;
}
__device__ __forceinline__ void ldsm_x4(uint32_t r[4], uint32_t addr) {
    asm volatile("ldmatrix.sync.aligned.m8n8.x4.shared.b16 {%0,%1,%2,%3}, [%4];"
                 : "=r"(r[0]), "=r"(r[1]), "=r"(r[2]), "=r"(r[3]) : "r"(addr));
}
__device__ __forceinline__ void mma_bf16(float c[4], const uint32_t a[4], uint32_t b0, uint32_t b1) {
    asm volatile("mma.sync.aligned.m16n8k16.row.col.f32.bf16.bf16.f32 "
                 "{%0,%1,%2,%3}, {%4,%5,%6,%7}, {%8,%9}, {%0,%1,%2,%3};"
                 : "+f"(c[0]), "+f"(c[1]), "+f"(c[2]), "+f"(c[3])
                 : "r"(a[0]), "r"(a[1]), "r"(a[2]), "r"(a[3]), "r"(b0), "r"(b1));
}
__device__ __forceinline__ uint32_t pkb(__nv_bfloat16 a, __nv_bfloat16 b) {
    return (uint32_t)__bfloat16_as_ushort(a) | ((uint32_t)__bfloat16_as_ushort(b) << 16);
}
#define CP16(dst, src) \
    asm volatile("cp.async.ca.shared.global [%0], [%1], 16;" :: "r"((uint32_t)(dst)), "l"(src))
#define CP_COMMIT() asm volatile("cp.async.commit_group;")
#define CP_WAIT0()  asm volatile("cp.async.wait_group 0;" ::: "memory")
#define CP_WAIT1()  asm volatile("cp.async.wait_group 1;" ::: "memory")

// ---------------- scratch ----------------
__device__ float    g_xm  [NPTS * CIN];     // LN(M) fp32, [p][c]
__device__ uint32_t g_xfh [NPTS * 64];      // LN(F) bf16 split, [p][word]: 0-31 hi pairs, 32-63 lo pairs
__device__ float    g_qm  [NPTS * CQ];      // float2 planes: [(h*32+c2)][p][2]
__device__ uint32_t g_GtA [CQ * 64];        // [n][word]: [hi | lo]
__device__ uint32_t g_GtB [CQ * 64];        // [n][word]: [lo | hi]
__device__ float    g_u   [CQ];

// ---------------- kernel 0: fused weights G = Wf Wm^T (bf16 split) + u ----------------
__global__ __launch_bounds__(256) void precompute_kernel(
    const float* __restrict__ wf, const float* __restrict__ wm,
    const float* __restrict__ bf)
{
    int h = blockIdx.x;
    __shared__ float wfs[64][65];
    __shared__ float wms[64][65];
    int tid = threadIdx.x;
    for (int idx = tid; idx < 4096; idx += 256) {
        int r = idx >> 6, d = idx & 63;
        wfs[r][d] = wf[r * CQ + h * 64 + d];
        wms[r][d] = wm[r * CQ + h * 64 + d];
    }
    __syncthreads();
    for (int idx = tid; idx < 2048; idx += 256) {
        int i2 = idx >> 6, j = idx & 63;
        float s0 = 0.f, s1 = 0.f;
        #pragma unroll
        for (int d = 0; d < 64; d++) {
            s0 += wfs[2 * i2][d] * wms[j][d];
            s1 += wfs[2 * i2 + 1][d] * wms[j][d];
        }
        __nv_bfloat16 h0 = __float2bfloat16_rn(s0), h1 = __float2bfloat16_rn(s1);
        __nv_bfloat16 l0 = __float2bfloat16_rn(s0 - __bfloat162float(h0));
        __nv_bfloat16 l1 = __float2bfloat16_rn(s1 - __bfloat162float(h1));
        int n = h * 64 + j;
        uint32_t hp = pkb(h0, h1), lp = pkb(l0, l1);
        g_GtA[n * 64 + i2]      = hp;
        g_GtA[n * 64 + 32 + i2] = lp;
        g_GtB[n * 64 + i2]      = lp;
        g_GtB[n * 64 + 32 + i2] = hp;
    }
    if (tid < 64) {
        float s = 0.f;
        #pragma unroll
        for (int d = 0; d < 64; d++) s += wms[tid][d] * bf[h * 64 + d];
        g_u[h * 64 + tid] = s;
    }
}

// ---------------- kernel 1: LayerNorm ----------------
__global__ __launch_bounds__(128) void ln_kernel(
    const float* __restrict__ src,
    const float* __restrict__ gamma, const float* __restrict__ beta,
    int which)   // 0 -> bf16 split to g_xfh ; 1 -> fp32 to g_xm
{
    __shared__ float gs[64], bs[64];
    int tid = threadIdx.x;
    if (tid < 64) { gs[tid] = gamma[tid]; bs[tid] = beta[tid]; }
    __syncthreads();

    int p = blockIdx.x * 128 + tid;
    float v[64];
    float mean = 0.f;
    #pragma unroll
    for (int c = 0; c < 64; c++) { v[c] = src[c * NPTS + p]; mean += v[c]; }
    mean *= (1.f / 64.f);
    float var = 0.f;
    #pragma unroll
    for (int c = 0; c < 64; c++) { float d = v[c] - mean; var += d * d; }
    float rstd = rsqrtf(var * (1.f / 64.f) + LNEPS);

    if (which == 0) {
        #pragma unroll
        for (int c8 = 0; c8 < 64; c8 += 8) {
            uint32_t hw[4], lw[4];
            #pragma unroll
            for (int j = 0; j < 4; j++) {
                int c = c8 + 2 * j;
                float y0 = (v[c] - mean) * rstd * gs[c] + bs[c];
                float y1 = (v[c + 1] - mean) * rstd * gs[c + 1] + bs[c + 1];
                __nv_bfloat16 h0 = __float2bfloat16_rn(y0), h1 = __float2bfloat16_rn(y1);
                __nv_bfloat16 l0 = __float2bfloat16_rn(y0 - __bfloat162float(h0));
                __nv_bfloat16 l1 = __float2bfloat16_rn(y1 - __bfloat162float(h1));
                hw[j] = pkb(h0, h1);
                lw[j] = pkb(l0, l1);
            }
            *(uint4*)&g_xfh[p * 64 + (c8 >> 1)]      = make_uint4(hw[0], hw[1], hw[2], hw[3]);
            *(uint4*)&g_xfh[p * 64 + 32 + (c8 >> 1)] = make_uint4(lw[0], lw[1], lw[2], lw[3]);
        }
    } else {
        #pragma unroll
        for (int c = 0; c < 64; c += 4) {
            float4 o;
            o.x = (v[c + 0] - mean) * rstd * gs[c + 0] + bs[c + 0];
            o.y = (v[c + 1] - mean) * rstd * gs[c + 1] + bs[c + 1];
            o.z = (v[c + 2] - mean) * rstd * gs[c + 2] + bs[c + 2];
            o.w = (v[c + 3] - mean) * rstd * gs[c + 3] + bs[c + 3];
            *(float4*)&g_xm[p * 64 + c] = o;
        }
    }
}

// ---------------- kernel 2: qm GEMM via mma.sync bf16 (split, exact) ----------------
// B-resident m-loop (unchanged from R6: ~69us).
#define GEMM_SMEM (98304)

__global__ __launch_bounds__(256, 2) void qm_gemm_mma()
{
    extern __shared__ char smg[];
    __shared__ float su[128];
    int tid = threadIdx.x;
    int wid = tid >> 5, lane = tid & 31;
    int n0 = blockIdx.x * 128;
    int p0 = blockIdx.y * 512;
    int wm = wid & 1, wn = wid >> 1;

    if (tid < 128) su[tid] = g_u[n0 + tid];

    uint32_t smb = smem_u32(smg);
    const uint4* xf4 = (const uint4*)g_xfh;
    const uint4* GA  = (const uint4*)g_GtA;
    const uint4* GB  = (const uint4*)g_GtB;

    #pragma unroll
    for (int i = tid; i < 2048; i += 256) {
        int r = i >> 4, c = i & 15;
        uint32_t dst = r * 256 + ((c ^ (r & 7)) << 4);
        CP16(smb + 32768 + dst, &GA[(n0 + r) * 16 + c]);
        CP16(smb + 65536 + dst, &GB[(n0 + r) * 16 + c]);
    }
    #pragma unroll
    for (int i = tid; i < 1024; i += 256) {
        int r = i >> 4, c = i & 15;
        uint32_t dst = r * 256 + ((c ^ (r & 7)) << 4);
        CP16(smb + dst, &xf4[(p0 + r) * 16 + c]);
    }
    CP_COMMIT();

    int arow = wm * 32 + (lane & 15);
    int ach  = lane >> 4;
    int brow = wn * 32 + (lane & 7) + ((lane >> 4) << 3);
    int bch  = (lane >> 3) & 1;
    int g = lane >> 2, t4 = lane & 3;
    float2* q2 = (float2*)g_qm;

    #pragma unroll 1
    for (int t = 0; t < 8; t++) {
        __syncthreads();
        if (t < 7) {
            uint32_t abase = ((t + 1) & 1) ? 16384u : 0u;
            int pr = p0 + (t + 1) * 64;
            #pragma unroll
            for (int i = tid; i < 1024; i += 256) {
                int r = i >> 4, c = i & 15;
                uint32_t dst = abase + r * 256 + ((c ^ (r & 7)) << 4);
                CP16(smb + dst, &xf4[(pr + r) * 16 + c]);
            }
            CP_COMMIT();
            CP_WAIT1();
        } else {
            CP_WAIT0();
        }
        __syncthreads();

        uint32_t abase = (t & 1) ? 16384u : 0u;
        float acc[2][4][4];
        #pragma unroll
        for (int mi = 0; mi < 2; mi++)
            #pragma unroll
            for (int ni = 0; ni < 4; ni++)
                #pragma unroll
                for (int e = 0; e < 4; e++) acc[mi][ni][e] = 0.f;

        #pragma unroll
        for (int ks = 0; ks < 16; ks++) {
            int kk = ks & 7;
            uint32_t boff = (ks < 8) ? 32768u : 65536u;
            uint32_t a[2][4];
            #pragma unroll
            for (int mi = 0; mi < 2; mi++) {
                int row = arow + mi * 16;
                int ch  = kk * 2 + ach;
                ldsm_x4(a[mi], smb + abase + row * 256 + ((ch ^ (row & 7)) << 4));
            }
            uint32_t b[2][4];
            #pragma unroll
            for (int nj = 0; nj < 2; nj++) {
                int row = brow + nj * 16;
                int ch  = kk * 2 + bch;
                ldsm_x4(b[nj], smb + boff + row * 256 + ((ch ^ (row & 7)) << 4));
            }
            #pragma unroll
            for (int mi = 0; mi < 2; mi++)
                #pragma unroll
                for (int nj = 0; nj < 2; nj++) {
                    mma_bf16(acc[mi][2 * nj + 0], a[mi], b[nj][0], b[nj][1]);
                    mma_bf16(acc[mi][2 * nj + 1], a[mi], b[nj][2], b[nj][3]);
                }
        }

        #pragma unroll
        for (int mi = 0; mi < 2; mi++) {
            int pA = p0 + t * 64 + wm * 32 + mi * 16 + g;
            #pragma unroll
            for (int ni = 0; ni < 4; ni++) {
                int nl = wn * 32 + ni * 8 + 2 * t4;
                int ng = n0 + nl;
                int h = ng >> 6, c2 = (ng & 63) >> 1;
                long base = (long)(h * 32 + c2) * NPTS;
                float u0 = su[nl], u1 = su[nl + 1];
                q2[base + pA]     = make_float2(acc[mi][ni][0] + u0, acc[mi][ni][1] + u1);
                q2[base + pA + 8] = make_float2(acc[mi][ni][2] + u0, acc[mi][ni][3] + u1);
            }
        }
    }
}

// ---------------- kernel 3: neighborhood attention (R6 layout + row pipelining) ----------------
// 512 thr, tile 2z x 2y x 32t, halo [c4=16][hz4][hy4][ht34] float4 (139 KB).
// Inner loop software-pipelined at (dz,dy)-row granularity: load row r+1
// (3x LDS.128) interleaved with FMA of row r (24 FFMA) to break warp phase-lock
// between the LDS-burst and FFMA-burst phases.
__global__ __launch_bounds__(512) void attn_kernel(
    const float* __restrict__ rpb, float* __restrict__ out)
{
    extern __shared__ float4 halo[];    // [c4=16][hz=4][hy=4][ht=34]
    __shared__ float rpb_s[NHD * 27];

    int tid = threadIdx.x;
    int z0 = (blockIdx.x >> 4) * 2;
    int y0 = (blockIdx.x & 15) * 2;

    for (int i = tid; i < NHD * 27; i += 512) rpb_s[i] = rpb[i];

    const float4* xm4 = (const float4*)g_xm;
    for (int i = tid; i < 8704; i += 512) {
        int c4 = i / 544;
        int r  = i - c4 * 544;
        int hz = r / 136;
        int r2 = r - hz * 136;
        int hy = r2 / 34;
        int ht = r2 - hy * 34;
        int gz = z0 - 1 + hz, gy = y0 - 1 + hy, gt = ht - 1;
        float4 v = make_float4(0.f, 0.f, 0.f, 0.f);
        if ((unsigned)gz < 32u && (unsigned)gy < 32u && (unsigned)gt < 32u)
            v = xm4[(gz * 1024 + gy * 32 + gt) * 16 + c4];
        halo[((c4 * 4 + hz) * 4 + hy) * 34 + ht] = v;
    }
    __syncthreads();

    int quarter = tid >> 7;
    int ptid = tid & 127;
    int pz = ptid >> 6, py = (ptid >> 5) & 1, pt = ptid & 31;
    int gp = (z0 + pz) * 1024 + (y0 + py) * 32 + pt;
    const float2* qm2 = (const float2*)g_qm;

    #pragma unroll 1
    for (int hg = 0; hg < 2; hg++) {
        int h0 = 2 * (quarter + 4 * hg);    // head pair {h0, h0+1}

        float sc0[27], sc1[27];
        #pragma unroll
        for (int o = 0; o < 27; o++) {
            sc0[o] = rpb_s[h0 * 27 + o];
            sc1[o] = rpb_s[(h0 + 1) * 27 + o];
        }

        float2 a0 = qm2[(h0 * 32 + 0) * NPTS + gp];
        float2 a1 = qm2[(h0 * 32 + 1) * NPTS + gp];
        float2 b0 = qm2[((h0 + 1) * 32 + 0) * NPTS + gp];
        float2 b1 = qm2[((h0 + 1) * 32 + 1) * NPTS + gp];
        float4 q0 = make_float4(a0.x, a0.y, a1.x, a1.y);
        float4 q1 = make_float4(b0.x, b0.y, b1.x, b1.y);
        float4 q0n, q1n;

        #pragma unroll 1
        for (int c4 = 0; c4 < 16; c4++) {
            if (c4 < 15) {
                float2 c0 = qm2[(h0 * 32 + 2 * c4 + 2) * NPTS + gp];
                float2 c1 = qm2[(h0 * 32 + 2 * c4 + 3) * NPTS + gp];
                float2 d0 = qm2[((h0 + 1) * 32 + 2 * c4 + 2) * NPTS + gp];
                float2 d1 = qm2[((h0 + 1) * 32 + 2 * c4 + 3) * NPTS + gp];
                q0n = make_float4(c0.x, c0.y, c1.x, c1.y);
                q1n = make_float4(d0.x, d0.y, d1.x, d1.y);
            }

            // ---- row-pipelined QK: 9 rows of (3 loads + 24 FFMA) ----
            const float4* rp0 = &halo[((c4 * 4 + pz) * 4 + py) * 34 + pt];
            float4 n0v = rp0[0], n1v = rp0[1], n2v = rp0[2];
            #pragma unroll
            for (int r = 0; r < 9; r++) {
                float4 k0 = n0v, k1 = n1v, k2 = n2v;
                if (r < 8) {
                    int rn = r + 1;
                    int dzn = rn / 3, dyn = rn - dzn * 3;
                    const float4* np = &halo[((c4 * 4 + pz + dzn) * 4 + (py + dyn)) * 34 + pt];
                    n0v = np[0]; n1v = np[1]; n2v = np[2];
                }
                int ob = r * 3;
                // dx = 0
                sc0[ob + 0] = fmaf(q0.x, k0.x, sc0[ob + 0]);
                sc1[ob + 0] = fmaf(q1.x, k0.x, sc1[ob + 0]);
                sc0[ob + 0] = fmaf(q0.y, k0.y, sc0[ob + 0]);
                sc1[ob + 0] = fmaf(q1.y, k0.y, sc1[ob + 0]);
                sc0[ob + 0] = fmaf(q0.z, k0.z, sc0[ob + 0]);
                sc1[ob + 0] = fmaf(q1.z, k0.z, sc1[ob + 0]);
                sc0[ob + 0] = fmaf(q0.w, k0.w, sc0[ob + 0]);
                sc1[ob + 0] = fmaf(q1.w, k0.w, sc1[ob + 0]);
                // dx = 1
                sc0[ob + 1] = fmaf(q0.x, k1.x, sc0[ob + 1]);
                sc1[ob + 1] = fmaf(q1.x, k1.x, sc1[ob + 1]);
                sc0[ob + 1] = fmaf(q0.y, k1.y, sc0[ob + 1]);
                sc1[ob + 1] = fmaf(q1.y, k1.y, sc1[ob + 1]);
                sc0[ob + 1] = fmaf(q0.z, k1.z, sc0[ob + 1]);
                sc1[ob + 1] = fmaf(q1.z, k1.z, sc1[ob + 1]);
                sc0[ob + 1] = fmaf(q0.w, k1.w, sc0[ob + 1]);
                sc1[ob + 1] = fmaf(q1.w, k1.w, sc1[ob + 1]);
                // dx = 2
                sc0[ob + 2] = fmaf(q0.x, k2.x, sc0[ob + 2]);
                sc1[ob + 2] = fmaf(q1.x, k2.x, sc1[ob + 2]);
                sc0[ob + 2] = fmaf(q0.y, k2.y, sc0[ob + 2]);
                sc1[ob + 2] = fmaf(q1.y, k2.y, sc1[ob + 2]);
                sc0[ob + 2] = fmaf(q0.z, k2.z, sc0[ob + 2]);
                sc1[ob + 2] = fmaf(q1.z, k2.z, sc1[ob + 2]);
                sc0[ob + 2] = fmaf(q0.w, k2.w, sc0[ob + 2]);
                sc1[ob + 2] = fmaf(q1.w, k2.w, sc1[ob + 2]);
            }
            q0 = q0n; q1 = q1n;
        }

        #pragma unroll
        for (int w = 0; w < 2; w++) {
            const float* s = w ? sc1 : sc0;
            int h = h0 + w;
            float m = s[0];
            #pragma unroll
            for (int o = 1; o < 27; o++) m = fmaxf(m, s[o]);
            float sum = 0.f, xz = 0.f, xy = 0.f, xt = 0.f;
            #pragma unroll
            for (int dz = 0; dz < 3; dz++)
                #pragma unroll
                for (int dy = 0; dy < 3; dy++)
                    #pragma unroll
                    for (int dx = 0; dx < 3; dx++) {
                        int o = (dz * 3 + dy) * 3 + dx;
                        float e = __expf(s[o] - m);
                        sum += e;
                        xz += e * (float)(dz - 1);
                        xy += e * (float)(dy - 1);
                        xt += e * (float)(dx - 1);
                    }
            float inv = 1.f / sum;
            out[(h * 3 + 0) * NPTS + gp] = xz * inv;
            out[(h * 3 + 1) * NPTS + gp] = xy * inv;
            out[(h * 3 + 2) * NPTS + gp] = xt * inv;
        }
    }
}

// ---------------- launch ----------------
extern "C" void kernel_launch(void* const* d_in, const int* in_sizes, int n_in,
                              void* d_out, int out_size)
{
    const float* F       = (const float*)d_in[0];
    const float* M       = (const float*)d_in[1];
    const float* gamma_f = (const float*)d_in[2];
    const float* beta_f  = (const float*)d_in[3];
    const float* w_f     = (const float*)d_in[4];
    const float* b_f     = (const float*)d_in[5];
    const float* gamma_m = (const float*)d_in[6];
    const float* beta_m  = (const float*)d_in[7];
    const float* w_m     = (const float*)d_in[8];
    /* b_m (d_in[9]) is softmax-invariant and drops out */
    const float* rpb     = (const float*)d_in[10];
    float* out = (float*)d_out;

    precompute_kernel<<<16, 256>>>(w_f, w_m, b_f);
    ln_kernel<<<NPTS / 128, 128>>>(F, gamma_f, beta_f, 0);
    ln_kernel<<<NPTS / 128, 128>>>(M, gamma_m, beta_m, 1);

    cudaFuncSetAttribute(qm_gemm_mma, cudaFuncAttributeMaxDynamicSharedMemorySize, GEMM_SMEM);
    qm_gemm_mma<<<dim3(8, 64), 256, GEMM_SMEM>>>();

    const int haloBytes = 16 * 4 * 4 * 34 * (int)sizeof(float4);   // 139264
    cudaFuncSetAttribute(attn_kernel, cudaFuncAttributeMaxDynamicSharedMemorySize, haloBytes);
    attn_kernel<<<256, 512, haloBytes>>>(rpb, out);
}